// round 6
// baseline (speedup 1.0000x reference)
#include <cuda_runtime.h>

// Problem constants (N_ATOMS = 128, fixed by the reference)
#define NA      128
#define NSEG    7875          // sum_{i=0}^{124} (125 - i)
#define OUTPB   16256         // n^2 - n  (all off-diagonal cells, row-major)
#define MAXB    512
#define SDIM    130           // padded symmetric matrix, zero border

// Scratch: per-batch padded symmetric segment-writhe matrix (~34.6 MB).
// Zero-initialized at module load. writhe writes upper (col-row>=2) cells only;
// mirror copies upper -> lower each launch. All other cells stay 0 forever.
__device__ float g_S[(size_t)MAXB * SDIM * SDIM];

// off(i) = number of segments with first index < i  (n = 128)
__device__ __forceinline__ int seg_off(int i) { return (i * (251 - i)) >> 1; }

// Branch-free asin via Abramowitz & Stegun 4.4.46 (|eps| ~ 1e-7 in float)
__device__ __forceinline__ float fast_asin(float x)
{
    const float a = fabsf(x);
    float p = fmaf(a, -0.0012624911f, 0.0066700901f);
    p = fmaf(a, p, -0.0170881256f);
    p = fmaf(a, p,  0.0308918810f);
    p = fmaf(a, p, -0.0501743046f);
    p = fmaf(a, p,  0.0889789874f);
    p = fmaf(a, p, -0.2145988016f);
    p = fmaf(a, p,  1.5707963050f);
    const float om = 1.0f - a;                       // >= 0 (input clamped)
    const float s  = om * rsqrtf(fmaxf(om, 1e-38f)); // sqrt(om) via MUFU
    return copysignf(1.5707963268f - s * p, x);
}

// -------------------------------------------------------------------------
// Kernel 1: writhe per (batch, segment); coalesced upper-triangle store ONLY.
// -------------------------------------------------------------------------
__global__ __launch_bounds__(256) void writhe_kernel(const float* __restrict__ xyz)
{
    __shared__ float4 pt[NA];
    const int b = blockIdx.y;
    const float* x = xyz + (size_t)b * NA * 3;
    for (int t = threadIdx.x; t < NA; t += blockDim.x)
        pt[t] = make_float4(x[3 * t + 0], x[3 * t + 1], x[3 * t + 2], 0.0f);
    __syncthreads();

    const int s = blockIdx.x * blockDim.x + threadIdx.x;
    if (s >= NSEG) return;

    // invert s -> (i, j):  largest i with seg_off(i) <= s
    int i = (int)((251.0f - sqrtf(63001.0f - 8.0f * (float)s)) * 0.5f);
    if (i < 0) i = 0;
    if (i > 124) i = 124;
    while (i < 124 && seg_off(i + 1) <= s) i++;
    while (i > 0 && seg_off(i) > s) i--;
    const int j = s - seg_off(i) + i + 2;

    const float4 P0 = pt[i];
    const float4 P1 = pt[i + 1];
    const float4 P2 = pt[j];
    const float4 P3 = pt[j + 1];

    // unnormalized directions (normalization is redundant)
    const float d0x = P2.x - P0.x, d0y = P2.y - P0.y, d0z = P2.z - P0.z;
    const float d1x = P3.x - P0.x, d1y = P3.y - P0.y, d1z = P3.z - P0.z;
    const float d2x = P2.x - P1.x, d2y = P2.y - P1.y, d2z = P2.z - P1.z;
    const float d3x = P3.x - P1.x, d3y = P3.y - P1.y, d3z = P3.z - P1.z;

    // c0 = d0 x d1, c1 = d1 x d3, c2 = d3 x d2, c3 = d2 x d0
    const float c0x = d0y * d1z - d0z * d1y;
    const float c0y = d0z * d1x - d0x * d1z;
    const float c0z = d0x * d1y - d0y * d1x;

    const float c1x = d1y * d3z - d1z * d3y;
    const float c1y = d1z * d3x - d1x * d3z;
    const float c1z = d1x * d3y - d1y * d3x;

    const float c2x = d3y * d2z - d3z * d2y;
    const float c2y = d3z * d2x - d3x * d2z;
    const float c2z = d3x * d2y - d3y * d2x;

    const float c3x = d2y * d0z - d2z * d0y;
    const float c3y = d2z * d0x - d2x * d0z;
    const float c3z = d2x * d0y - d2y * d0x;

    // sign: dot(axial, d0) == -det[d0, d1, d2] == -(d2 . c0)
    const float dp = -(d2x * c0x + d2y * c0y + d2z * c0z);
    const float sg = (dp > 0.0f) ? 1.0f : ((dp < 0.0f) ? -1.0f : 0.0f);

    const float r0 = rsqrtf(c0x * c0x + c0y * c0y + c0z * c0z);
    const float r1 = rsqrtf(c1x * c1x + c1y * c1y + c1z * c1z);
    const float r2 = rsqrtf(c2x * c2x + c2y * c2y + c2z * c2z);
    const float r3 = rsqrtf(c3x * c3x + c3y * c3y + c3z * c3z);

    float q0 = (c0x * c1x + c0y * c1y + c0z * c1z) * r0 * r1;
    float q1 = (c1x * c2x + c1y * c2y + c1z * c2z) * r1 * r2;
    float q2 = (c2x * c3x + c2y * c3y + c2z * c3z) * r2 * r3;
    float q3 = (c3x * c0x + c3y * c0y + c3z * c0z) * r3 * r0;

    q0 = fminf(fmaxf(q0, -1.0f), 1.0f);
    q1 = fminf(fmaxf(q1, -1.0f), 1.0f);
    q2 = fminf(fmaxf(q2, -1.0f), 1.0f);
    q3 = fminf(fmaxf(q3, -1.0f), 1.0f);

    const float omega = fast_asin(q0) + fast_asin(q1) +
                        fast_asin(q2) + fast_asin(q3);
    const float wr = omega * sg * 0.15915494309189535f; // 1/(2*pi)

    g_S[(size_t)b * SDIM * SDIM + (i + 1) * SDIM + (j + 1)] = wr; // coalesced
}

// -------------------------------------------------------------------------
// Kernel 2: smem-tiled mirror (upper -> lower), both directions coalesced.
// Lower-triangle tiles (tr >= tc) of the 5x5 32-tile grid over SDIM=130.
// -------------------------------------------------------------------------
__constant__ int TR_TAB[15] = {0,1,1,2,2,2,3,3,3,3,4,4,4,4,4};
__constant__ int TC_TAB[15] = {0,0,1,0,1,2,0,1,2,3,0,1,2,3,4};

__global__ __launch_bounds__(256) void mirror_kernel()
{
    __shared__ float tile[32][33];
    const int b  = blockIdx.y;
    const int tr = TR_TAB[blockIdx.x];
    const int tc = TC_TAB[blockIdx.x];
    float* S = g_S + (size_t)b * SDIM * SDIM;

    const int tx = threadIdx.x & 31;
    const int ty = threadIdx.x >> 5;

    // read upper source tile: rows 32*tc + u, cols 32*tr + v(=tx)
    #pragma unroll
    for (int k = 0; k < 4; ++k) {
        const int u   = ty + 8 * k;
        const int row = 32 * tc + u;
        const int col = 32 * tr + tx;
        tile[u][tx] = (row < SDIM && col < SDIM) ? S[row * SDIM + col] : 0.0f;
    }
    __syncthreads();

    // write lower dest tile: rows 32*tr + v, cols 32*tc + u(=tx)
    #pragma unroll
    for (int k = 0; k < 4; ++k) {
        const int v   = ty + 8 * k;
        const int row = 32 * tr + v;
        const int col = 32 * tc + tx;
        if (row < SDIM && col < SDIM && row > col)
            S[row * SDIM + col] = tile[tx][v];
    }
}

// -------------------------------------------------------------------------
// Kernel 3: row-staged stencil gather.
// Block = (batch b, 8 output rows r0..r0+7). Stages S rows r0..r0+8
// (contiguous 1170 floats) into smem; each warp emits one output row.
// -------------------------------------------------------------------------
__global__ __launch_bounds__(256) void gather_kernel(float* __restrict__ out)
{
    __shared__ float sm[9 * SDIM];
    const int b  = blockIdx.y;
    const int r0 = blockIdx.x * 8;

    const float* Srows = g_S + (size_t)b * SDIM * SDIM + (size_t)r0 * SDIM;
    for (int idx = threadIdx.x; idx < 9 * SDIM; idx += 256)
        sm[idx] = Srows[idx];                    // fully coalesced stream
    __syncthreads();

    const int w    = threadIdx.x >> 5;           // 0..7: output row within tile
    const int lane = threadIdx.x & 31;
    const int r    = r0 + w;
    const float* row0 = sm + w * SDIM;           // S[r]
    const float* row1 = sm + (w + 1) * SDIM;     // S[r+1]
    float* orow = out + (size_t)b * OUTPB + (size_t)r * 127;

    #pragma unroll
    for (int e = 0; e < 4; ++e) {
        const int cp = lane + 32 * e;
        if (cp < 127) {
            const int c = cp + (cp >= r ? 1 : 0);
            orow[cp] = row1[c + 1] + row1[c] + row0[c + 1] + row0[c];
        }
    }
}

// -------------------------------------------------------------------------
extern "C" void kernel_launch(void* const* d_in, const int* in_sizes, int n_in,
                              void* d_out, int out_size)
{
    const float* xyz = (const float*)d_in[0];
    int B = in_sizes[0] / (NA * 3);
    if (B > MAXB) B = MAXB;

    dim3 gw((NSEG + 255) / 256, B);
    writhe_kernel<<<gw, 256>>>(xyz);

    dim3 gm(15, B);
    mirror_kernel<<<gm, 256>>>();

    dim3 gg(16, B);
    gather_kernel<<<gg, 256>>>((float*)d_out);
}